// round 16
// baseline (speedup 1.0000x reference)
#include <cuda_runtime.h>

// Problem constants (fixed by the dataset shapes)
#define B_      8
#define NHEADS  4
#define Q_      512      // codebook entries per head (N/4)
#define L_      2048     // sequence length (innermost logits dim)
#define D_      512      // embedding dim
#define K_      3        // top-k

// ---------------- kernel A config ----------------
#define LTA      32      // l-tile per block
#define NTHRA    512
#define SEGS     4       // n-range split per (h,l)
#define NSEG     (Q_ / SEGS)   // 128

// ---------------- kernel B config ----------------
#define LTB      32              // l-tile per block
#define NTHRB    256             // 8 warps
#define DCHUNK   128             // dd per round (float4: 32 lanes x 4)
#define NROUND   (D_ / DCHUNK)   // 4
#define TPITCH   132             // tile pitch: 33 float4s; 33 mod 32 = 1 ->
                                 // column-wise float4 reads are conflict-free

// Scratch: (idx pre-scaled to float4 row base, w) per (b,h,l,k). 1.5 MB total.
__device__ int   g_idx[B_ * NHEADS * L_ * K_];
__device__ float g_w  [B_ * NHEADS * L_ * K_];

// Branchless top-3 insert: 3 independent FSETP (pred-as-data, 4 cyc) +
// 10 selects, all fixed-latency 4-cyc class. No branches, no divergence,
// no 13-cyc pred-as-guard serialization. Exact (no precision change).
// Predicates are computed from the OLD state; updates cascade t2<-t1<-t0.
#define TOP3_BL(v, n)                                                  \
    do {                                                               \
        bool p0 = (v) > t0;                                            \
        bool p1 = (v) > t1;                                            \
        bool p2 = (v) > t2;                                            \
        t2 = p1 ? t1 : (p2 ? (v) : t2);                                \
        i2 = p1 ? i1 : (p2 ? (n) : i2);                                \
        t1 = p0 ? t0 : (p1 ? (v) : t1);                                \
        i1 = p0 ? i0 : (p1 ? (n) : i1);                                \
        t0 = p0 ? (v) : t0;                                            \
        i0 = p0 ? (n) : i0;                                            \
    } while (0)

// ======================= kernel A: top-3 + softmax =======================
__global__ __launch_bounds__(NTHRA)
void topk_softmax(const float* __restrict__ logits)
{
    const int b   = blockIdx.y;
    const int l0  = blockIdx.x * LTA;
    const int tid = threadIdx.x;

    // partial top-3 from segments 1..3 (segment 0 stays in the merger's regs)
    __shared__ float s_pv[SEGS - 1][NHEADS][LTA][K_];
    __shared__ int   s_pi[SEGS - 1][NHEADS][LTA][K_];

    const int l   = tid & (LTA - 1);           // 0..31
    const int h   = (tid >> 5) & (NHEADS - 1); // 0..3
    const int seg = tid >> 7;                  // 0..3
    const int nb  = seg * NSEG;

    const float* p = logits
        + ((size_t)b * (NHEADS * Q_) + (size_t)h * Q_ + nb) * L_ + l0 + l;

    float t0 = -3.4e38f, t1 = -3.4e38f, t2 = -3.4e38f;
    int   i0 = 0, i1 = 0, i2 = 0;

    // 8 loads per iter with CONSTANT offsets (fits LDG immediate) + one
    // pointer bump; then 8 branchless inserts (pure 4-cyc select network).
    for (int n = 0; n < NSEG; n += 8) {
        float v0 = __ldg(p + 0 * L_);
        float v1 = __ldg(p + 1 * L_);
        float v2 = __ldg(p + 2 * L_);
        float v3 = __ldg(p + 3 * L_);
        float v4 = __ldg(p + 4 * L_);
        float v5 = __ldg(p + 5 * L_);
        float v6 = __ldg(p + 6 * L_);
        float v7 = __ldg(p + 7 * L_);
        p += 8 * L_;
        TOP3_BL(v0, nb + n + 0);
        TOP3_BL(v1, nb + n + 1);
        TOP3_BL(v2, nb + n + 2);
        TOP3_BL(v3, nb + n + 3);
        TOP3_BL(v4, nb + n + 4);
        TOP3_BL(v5, nb + n + 5);
        TOP3_BL(v6, nb + n + 6);
        TOP3_BL(v7, nb + n + 7);
    }

    if (seg > 0) {
        s_pv[seg - 1][h][l][0] = t0;  s_pi[seg - 1][h][l][0] = i0;
        s_pv[seg - 1][h][l][1] = t1;  s_pi[seg - 1][h][l][1] = i1;
        s_pv[seg - 1][h][l][2] = t2;  s_pi[seg - 1][h][l][2] = i2;
    }
    __syncthreads();

    if (seg == 0) {
        #pragma unroll
        for (int s = 0; s < SEGS - 1; s++) {
            #pragma unroll
            for (int k = 0; k < K_; k++) {
                float v = s_pv[s][h][l][k];
                int   n = s_pi[s][h][l][k];
                TOP3_BL(v, n);
            }
        }
        float w1  = expf(t1 - t0);
        float w2  = expf(t2 - t0);
        float inv = 1.0f / (1.0f + w1 + w2);

        size_t base = (((size_t)b * NHEADS + h) * L_ + (l0 + l)) * K_;
        g_w[base + 0] = inv;
        g_w[base + 1] = w1 * inv;
        g_w[base + 2] = w2 * inv;
        // pre-scale index to float4-row offset (row = m * D_/4)
        g_idx[base + 0] = i0 * (D_ / 4);
        g_idx[base + 1] = i1 * (D_ / 4);
        g_idx[base + 2] = i2 * (D_ / 4);
    }
}

// =============== kernel B: gather-combine + transpose-out ===============
// UNCHANGED from R15 (measured at ~12 TB/s L2 traffic = chip LTS cap).
__global__ __launch_bounds__(NTHRB, 4)
void gather_combine(const float* __restrict__ e0,
                    const float* __restrict__ e1,
                    const float* __restrict__ e2,
                    const float* __restrict__ e3,
                    float* __restrict__ out)
{
    const int b   = blockIdx.y;
    const int l0  = blockIdx.x * LTB;
    const int tid = threadIdx.x;

    __shared__ int   s_idx[NHEADS][LTB][K_];     // 384 ints
    __shared__ float s_w  [NHEADS][LTB][K_];     // 384 floats
    __shared__ __align__(16) float tile[LTB][TPITCH];

    // stage this block's (idx, w): 384 entries, strided over 256 threads
    for (int i = tid; i < NHEADS * LTB * K_; i += NTHRB) {
        int h  = i / (LTB * K_);
        int r  = i - h * (LTB * K_);
        size_t g = (((size_t)b * NHEADS + h) * L_ + l0) * K_ + r;
        ((int*)  s_idx)[i] = g_idx[g];
        ((float*)s_w  )[i] = g_w  [g];
    }
    __syncthreads();

    const int warp = tid >> 5;   // 0..7
    const int lane = tid & 31;
    float* outb = out + (size_t)b * D_ * L_ + l0;

    #pragma unroll
    for (int r = 0; r < NROUND; r++) {
        const int c = r * (DCHUNK / 4) + lane;   // float4 column

        // one li at a time: 12 LDG.128 in flight per warp (ample MLP),
        // bounded live registers for the 4-blocks/SM target
        #pragma unroll 1
        for (int li = warp; li < LTB; li += NTHRB / 32) {
            float4 acc = make_float4(0.f, 0.f, 0.f, 0.f);
            #pragma unroll
            for (int h = 0; h < NHEADS; h++) {
                const float4* eh = (h == 0) ? (const float4*)e0
                                 : (h == 1) ? (const float4*)e1
                                 : (h == 2) ? (const float4*)e2
                                 :            (const float4*)e3;
                #pragma unroll
                for (int k = 0; k < K_; k++) {
                    int    mo = s_idx[h][li][k];    // already * D_/4
                    float  w  = s_w  [h][li][k];
                    float4 v  = __ldg(eh + mo + c);
                    acc.x = fmaf(w, v.x, acc.x);
                    acc.y = fmaf(w, v.y, acc.y);
                    acc.z = fmaf(w, v.z, acc.z);
                    acc.w = fmaf(w, v.w, acc.w);
                }
            }
            // STS.128, lanes contiguous -> conflict-free
            *(float4*)&tile[li][4 * lane] = acc;
        }
        __syncthreads();

        // write-out: LDS.128 at float4 addr l*33 + j (stride 33 = 1 mod 32,
        // conflict-free), then 4 coalesced STG.32 per thread (128B lines).
        #pragma unroll
        for (int it = 0; it < (DCHUNK / 4) * LTB / NTHRB; it++) {   // 4 iters
            int i = tid + it * NTHRB;
            int l = i & (LTB - 1);        // lane == l
            int j = i >> 5;               // float4 group 0..31
            float4 v = *(const float4*)&tile[l][4 * j];
            size_t dbase = (size_t)(r * DCHUNK + 4 * j) * L_ + l;
            outb[dbase + 0 * L_] = v.x;
            outb[dbase + 1 * L_] = v.y;
            outb[dbase + 2 * L_] = v.z;
            outb[dbase + 3 * L_] = v.w;
        }
        __syncthreads();
    }
}

extern "C" void kernel_launch(void* const* d_in, const int* in_sizes, int n_in,
                              void* d_out, int out_size)
{
    const float* logits = (const float*)d_in[0];
    const float* e0     = (const float*)d_in[1];
    const float* e1     = (const float*)d_in[2];
    const float* e2     = (const float*)d_in[3];
    const float* e3     = (const float*)d_in[4];
    float*       out    = (float*)d_out;

    dim3 gridA(L_ / LTA, B_);   // 64 x 8 = 512 blocks
    topk_softmax<<<gridA, NTHRA>>>(logits);

    dim3 gridB(L_ / LTB, B_);   // 64 x 8 = 512 blocks
    gather_combine<<<gridB, NTHRB>>>(e0, e1, e2, e3, out);
}

// round 17
// speedup vs baseline: 1.0275x; 1.0275x over previous
#include <cuda_runtime.h>

// Problem constants (fixed by the dataset shapes)
#define B_      8
#define NHEADS  4
#define Q_      512      // codebook entries per head (N/4)
#define L_      2048     // sequence length (innermost logits dim)
#define D_      512      // embedding dim
#define K_      3        // top-k

// ---------------- kernel A config ----------------
#define LTA      32      // l-tile per block
#define NTHRA    512
#define SEGS     4       // n-range split per (h,l)
#define NSEG     (Q_ / SEGS)   // 128
#define BATCH    8

// ---------------- kernel B config ----------------
#define LTB      32              // l-tile per block
#define NTHRB    256             // 8 warps
#define DCHUNK   128             // dd per round (float4: 32 lanes x 4)
#define NROUND   (D_ / DCHUNK)   // 4
#define TPITCH   132             // tile pitch: 33 float4s; 33 mod 32 = 1 ->
                                 // column-wise float4 reads are conflict-free

// Scratch: (idx pre-scaled to float4 row base, w) per (b,h,l,k). 1.5 MB total.
__device__ int   g_idx[B_ * NHEADS * L_ * K_];
__device__ float g_w  [B_ * NHEADS * L_ * K_];

// top-3 update, branch-light common path (best measured variant, R15)
#define TOP3_UPDATE(v, n)                                              \
    do {                                                               \
        if ((v) > t2) {                                                \
            if ((v) > t0)      { t2=t1; i2=i1; t1=t0; i1=i0; t0=(v); i0=(n); } \
            else if ((v) > t1) { t2=t1; i2=i1; t1=(v); i1=(n); }       \
            else               { t2=(v); i2=(n); }                     \
        }                                                              \
    } while (0)

// streaming load (evict-first): logits are touched exactly once
__device__ __forceinline__ float ldstream(const float* p) {
    return __ldcs(p);
}

// ======================= kernel A: top-3 + softmax =======================
__global__ __launch_bounds__(NTHRA)
void topk_softmax(const float* __restrict__ logits)
{
    const int b   = blockIdx.y;
    const int l0  = blockIdx.x * LTA;
    const int tid = threadIdx.x;

    // partial top-3 from segments 1..3 (segment 0 stays in the merger's regs)
    __shared__ float s_pv[SEGS - 1][NHEADS][LTA][K_];
    __shared__ int   s_pi[SEGS - 1][NHEADS][LTA][K_];

    const int l   = tid & (LTA - 1);           // 0..31
    const int h   = (tid >> 5) & (NHEADS - 1); // 0..3
    const int seg = tid >> 7;                  // 0..3
    const int nb  = seg * NSEG;

    const float* p = logits
        + ((size_t)b * (NHEADS * Q_) + (size_t)h * Q_ + nb) * L_ + l0 + l;

    float t0 = -3.4e38f, t1 = -3.4e38f, t2 = -3.4e38f;
    int   i0 = 0, i1 = 0, i2 = 0;

    // Software-pipelined scan: batch j+1's loads are issued BEFORE batch j's
    // branchy processing, so 8 lines/thread stay in flight through the
    // compare chain (ptxas won't hoist loads across the branches itself).
    float cur[BATCH];
    #pragma unroll
    for (int j = 0; j < BATCH; j++) cur[j] = ldstream(p + j * L_);
    p += BATCH * L_;

    #pragma unroll 1
    for (int n = 0; n < NSEG - BATCH; n += BATCH) {
        float nxt[BATCH];
        #pragma unroll
        for (int j = 0; j < BATCH; j++) nxt[j] = ldstream(p + j * L_);
        p += BATCH * L_;

        #pragma unroll
        for (int j = 0; j < BATCH; j++) TOP3_UPDATE(cur[j], nb + n + j);

        #pragma unroll
        for (int j = 0; j < BATCH; j++) cur[j] = nxt[j];
    }
    #pragma unroll
    for (int j = 0; j < BATCH; j++) TOP3_UPDATE(cur[j], nb + NSEG - BATCH + j);

    if (seg > 0) {
        s_pv[seg - 1][h][l][0] = t0;  s_pi[seg - 1][h][l][0] = i0;
        s_pv[seg - 1][h][l][1] = t1;  s_pi[seg - 1][h][l][1] = i1;
        s_pv[seg - 1][h][l][2] = t2;  s_pi[seg - 1][h][l][2] = i2;
    }
    __syncthreads();

    if (seg == 0) {
        #pragma unroll
        for (int s = 0; s < SEGS - 1; s++) {
            #pragma unroll
            for (int k = 0; k < K_; k++) {
                float v = s_pv[s][h][l][k];
                int   n = s_pi[s][h][l][k];
                TOP3_UPDATE(v, n);
            }
        }
        float w1  = expf(t1 - t0);
        float w2  = expf(t2 - t0);
        float inv = 1.0f / (1.0f + w1 + w2);

        size_t base = (((size_t)b * NHEADS + h) * L_ + (l0 + l)) * K_;
        g_w[base + 0] = inv;
        g_w[base + 1] = w1 * inv;
        g_w[base + 2] = w2 * inv;
        // pre-scale index to float4-row offset (row = m * D_/4)
        g_idx[base + 0] = i0 * (D_ / 4);
        g_idx[base + 1] = i1 * (D_ / 4);
        g_idx[base + 2] = i2 * (D_ / 4);
    }
}

// =============== kernel B: gather-combine + transpose-out ===============
// UNCHANGED from R15 (measured at ~12 TB/s L2 traffic = chip LTS cap).
__global__ __launch_bounds__(NTHRB, 4)
void gather_combine(const float* __restrict__ e0,
                    const float* __restrict__ e1,
                    const float* __restrict__ e2,
                    const float* __restrict__ e3,
                    float* __restrict__ out)
{
    const int b   = blockIdx.y;
    const int l0  = blockIdx.x * LTB;
    const int tid = threadIdx.x;

    __shared__ int   s_idx[NHEADS][LTB][K_];     // 384 ints
    __shared__ float s_w  [NHEADS][LTB][K_];     // 384 floats
    __shared__ __align__(16) float tile[LTB][TPITCH];

    // stage this block's (idx, w): 384 entries, strided over 256 threads
    for (int i = tid; i < NHEADS * LTB * K_; i += NTHRB) {
        int h  = i / (LTB * K_);
        int r  = i - h * (LTB * K_);
        size_t g = (((size_t)b * NHEADS + h) * L_ + l0) * K_ + r;
        ((int*)  s_idx)[i] = g_idx[g];
        ((float*)s_w  )[i] = g_w  [g];
    }
    __syncthreads();

    const int warp = tid >> 5;   // 0..7
    const int lane = tid & 31;
    float* outb = out + (size_t)b * D_ * L_ + l0;

    #pragma unroll
    for (int r = 0; r < NROUND; r++) {
        const int c = r * (DCHUNK / 4) + lane;   // float4 column

        // one li at a time: 12 LDG.128 in flight per warp (ample MLP),
        // bounded live registers for the 4-blocks/SM target
        #pragma unroll 1
        for (int li = warp; li < LTB; li += NTHRB / 32) {
            float4 acc = make_float4(0.f, 0.f, 0.f, 0.f);
            #pragma unroll
            for (int h = 0; h < NHEADS; h++) {
                const float4* eh = (h == 0) ? (const float4*)e0
                                 : (h == 1) ? (const float4*)e1
                                 : (h == 2) ? (const float4*)e2
                                 :            (const float4*)e3;
                #pragma unroll
                for (int k = 0; k < K_; k++) {
                    int    mo = s_idx[h][li][k];    // already * D_/4
                    float  w  = s_w  [h][li][k];
                    float4 v  = __ldg(eh + mo + c);
                    acc.x = fmaf(w, v.x, acc.x);
                    acc.y = fmaf(w, v.y, acc.y);
                    acc.z = fmaf(w, v.z, acc.z);
                    acc.w = fmaf(w, v.w, acc.w);
                }
            }
            // STS.128, lanes contiguous -> conflict-free
            *(float4*)&tile[li][4 * lane] = acc;
        }
        __syncthreads();

        // write-out: LDS.128 at float4 addr l*33 + j (stride 33 = 1 mod 32,
        // conflict-free), then 4 coalesced STG.32 per thread (128B lines).
        #pragma unroll
        for (int it = 0; it < (DCHUNK / 4) * LTB / NTHRB; it++) {   // 4 iters
            int i = tid + it * NTHRB;
            int l = i & (LTB - 1);        // lane == l
            int j = i >> 5;               // float4 group 0..31
            float4 v = *(const float4*)&tile[l][4 * j];
            size_t dbase = (size_t)(r * DCHUNK + 4 * j) * L_ + l;
            outb[dbase + 0 * L_] = v.x;
            outb[dbase + 1 * L_] = v.y;
            outb[dbase + 2 * L_] = v.z;
            outb[dbase + 3 * L_] = v.w;
        }
        __syncthreads();
    }
}

extern "C" void kernel_launch(void* const* d_in, const int* in_sizes, int n_in,
                              void* d_out, int out_size)
{
    const float* logits = (const float*)d_in[0];
    const float* e0     = (const float*)d_in[1];
    const float* e1     = (const float*)d_in[2];
    const float* e2     = (const float*)d_in[3];
    const float* e3     = (const float*)d_in[4];
    float*       out    = (float*)d_out;

    dim3 gridA(L_ / LTA, B_);   // 64 x 8 = 512 blocks
    topk_softmax<<<gridA, NTHRA>>>(logits);

    dim3 gridB(L_ / LTB, B_);   // 64 x 8 = 512 blocks
    gather_combine<<<gridB, NTHRB>>>(e0, e1, e2, e3, out);
}